// round 6
// baseline (speedup 1.0000x reference)
#include <cuda_runtime.h>
#include <cuda_bf16.h>

// Problem constants (fixed by the dataset).
#define E_CNT 500000
#define P_CNT 4000000
#define D_DIM 64
#define U_DIM 64

#define SCAN_BLK 1024
#define NSCAN ((E_CNT + SCAN_BLK - 1) / SCAN_BLK)   // 489

// Device scratch (no allocs allowed). Total ~22 MB.
__device__ int g_cnt[E_CNT];        // per-dst edge counts
__device__ int g_off[E_CNT];        // exclusive prefix (global)
__device__ int g_cursor[E_CNT];     // running cursors for reorder
__device__ int g_blocksum[NSCAN];
__device__ int g_srcs[P_CNT];       // src indices sorted by dst

// ---------------------------------------------------------------------------
// 1. Zero the histogram.
// ---------------------------------------------------------------------------
__global__ void k_zero_cnt() {
    int i = blockIdx.x * blockDim.x + threadIdx.x;       // int4 index
    const int n4 = E_CNT / 4;                            // 125000
    if (i < n4) reinterpret_cast<int4*>(g_cnt)[i] = make_int4(0, 0, 0, 0);
}

// ---------------------------------------------------------------------------
// 2. Histogram of destinations.
// ---------------------------------------------------------------------------
__global__ void __launch_bounds__(256) k_hist(const int2* __restrict__ nbr) {
    int p = blockIdx.x * blockDim.x + threadIdx.x;
    if (p < P_CNT) atomicAdd(&g_cnt[__ldg(&nbr[p]).x], 1);
}

// ---------------------------------------------------------------------------
// 3. Block-local exclusive scan (Hillis-Steele, 1024/block) + block sums.
// ---------------------------------------------------------------------------
__global__ void __launch_bounds__(SCAN_BLK) k_scan_block() {
    __shared__ int tmp[SCAN_BLK];
    int t = threadIdx.x;
    int gid = blockIdx.x * SCAN_BLK + t;
    int v = (gid < E_CNT) ? g_cnt[gid] : 0;
    tmp[t] = v;
    __syncthreads();
#pragma unroll
    for (int d = 1; d < SCAN_BLK; d <<= 1) {
        int x = (t >= d) ? tmp[t - d] : 0;
        __syncthreads();
        tmp[t] += x;
        __syncthreads();
    }
    if (gid < E_CNT) g_off[gid] = tmp[t] - v;            // exclusive, block-local
    if (t == SCAN_BLK - 1) g_blocksum[blockIdx.x] = tmp[t];
}

// ---------------------------------------------------------------------------
// 4. Globalize offsets; init cursors. The 489-entry blocksum prefix is
//    computed inline per block (warp 0: strided partials + warp reduce) —
//    removes the old single-block k_scan_sums serializer + one launch.
// ---------------------------------------------------------------------------
__global__ void __launch_bounds__(256) k_scan_add() {
    __shared__ int s_off;
    int sb = blockIdx.x >> 2;          // 256-block lives inside one 1024 scan block
    if (threadIdx.x < 32) {
        int acc = 0;
        for (int i = threadIdx.x; i < sb; i += 32) acc += __ldg(&g_blocksum[i]);
#pragma unroll
        for (int d = 16; d > 0; d >>= 1) acc += __shfl_xor_sync(~0u, acc, d);
        if (threadIdx.x == 0) s_off = acc;
    }
    __syncthreads();
    int i = blockIdx.x * blockDim.x + threadIdx.x;
    if (i < E_CNT) {
        int o = g_off[i] + s_off;
        g_off[i] = o;
        g_cursor[i] = o;
    }
}

// ---------------------------------------------------------------------------
// 5. Reorder: scatter src ids into dst-sorted order. Streaming writes.
// ---------------------------------------------------------------------------
__global__ void __launch_bounds__(256) k_reorder(const int2* __restrict__ nbr) {
    int p = blockIdx.x * blockDim.x + threadIdx.x;
    if (p < P_CNT) {
        int2 e = __ldg(&nbr[p]);
        int pos = atomicAdd(&g_cursor[e.x], 1);
        __stcs(&g_srcs[pos], e.y);
    }
}

// ---------------------------------------------------------------------------
// 6. Fused segmented-sum + GEMM + bias. 256 threads = 8 warps = 8 dsts/block.
//    Phase A: warp w aggregates its dst row; lane owns 2 cols (float2),
//    4-way unrolled gathers. g_srcs read with evict-first (read-once).
//    Phase B: k-TILED register K (16 at a time, 4 tiles) — drops live regs
//    from ~90 to ~50 so we get 4 blocks/SM instead of 2; barrier imbalance
//    is hidden by cross-block warps and the gather saturates LTS.
//    Output stored with __stcs to avoid evicting the L2-resident F table.
// ---------------------------------------------------------------------------
__global__ void __launch_bounds__(256) k_fused(
    const float2* __restrict__ F2, const float* __restrict__ Kmat,
    const float* __restrict__ bias, float* __restrict__ out) {
    __shared__ float S[8][64];

    int warp = threadIdx.x >> 5;
    int lane = threadIdx.x & 31;
    int dst = blockIdx.x * 8 + warp;

    // ---- Phase A: gather + accumulate ----
    int s = __ldg(&g_off[dst]);
    int e = (dst == E_CNT - 1) ? P_CNT : __ldg(&g_off[dst + 1]);

    float ax = 0.f, ay = 0.f;
    int i = s;
    for (; i + 4 <= e; i += 4) {
        int s0 = __ldcs(&g_srcs[i + 0]);
        int s1 = __ldcs(&g_srcs[i + 1]);
        int s2 = __ldcs(&g_srcs[i + 2]);
        int s3 = __ldcs(&g_srcs[i + 3]);
        float2 v0 = __ldg(&F2[(size_t)s0 * 32 + lane]);
        float2 v1 = __ldg(&F2[(size_t)s1 * 32 + lane]);
        float2 v2 = __ldg(&F2[(size_t)s2 * 32 + lane]);
        float2 v3 = __ldg(&F2[(size_t)s3 * 32 + lane]);
        ax += (v0.x + v1.x) + (v2.x + v3.x);
        ay += (v0.y + v1.y) + (v2.y + v3.y);
    }
    for (; i < e; i++) {
        int s0 = __ldcs(&g_srcs[i]);
        float2 v = __ldg(&F2[(size_t)s0 * 32 + lane]);
        ax += v.x;
        ay += v.y;
    }
    reinterpret_cast<float2*>(S[warp])[lane] = make_float2(ax, ay);
    __syncthreads();

    // ---- Phase B: out[row] = S[row] . K[:,u] + b, k-tiled (16 regs) ----
    int u = threadIdx.x & 63;
    int g = threadIdx.x >> 6;  // 0..3 -> rows 2g, 2g+1
    float b = __ldg(&bias[u]);

    const float4* R0 = reinterpret_cast<const float4*>(S[2 * g + 0]);
    const float4* R1 = reinterpret_cast<const float4*>(S[2 * g + 1]);
    float acc0 = b, acc1 = b;
#pragma unroll
    for (int t4 = 0; t4 < 4; t4++) {
        float Kt[16];
#pragma unroll
        for (int kk = 0; kk < 16; kk++)
            Kt[kk] = __ldg(&Kmat[(t4 * 16 + kk) * U_DIM + u]);
#pragma unroll
        for (int k4 = 0; k4 < 4; k4++) {
            float4 x = R0[t4 * 4 + k4];
            float4 y = R1[t4 * 4 + k4];
            acc0 = fmaf(x.x, Kt[4 * k4 + 0],
                   fmaf(x.y, Kt[4 * k4 + 1],
                   fmaf(x.z, Kt[4 * k4 + 2],
                   fmaf(x.w, Kt[4 * k4 + 3], acc0))));
            acc1 = fmaf(y.x, Kt[4 * k4 + 0],
                   fmaf(y.y, Kt[4 * k4 + 1],
                   fmaf(y.z, Kt[4 * k4 + 2],
                   fmaf(y.w, Kt[4 * k4 + 3], acc1))));
        }
    }

    size_t rowA = ((size_t)blockIdx.x * 8 + 2 * g) * U_DIM;
    __stcs(&out[rowA + u], acc0);
    __stcs(&out[rowA + U_DIM + u], acc1);
}

// ---------------------------------------------------------------------------
// Launch pipeline (graph-capturable: kernels only, no sync, no allocs).
// ---------------------------------------------------------------------------
extern "C" void kernel_launch(void* const* d_in, const int* in_sizes, int n_in,
                              void* d_out, int out_size) {
    const float* feat = (const float*)d_in[0];   // [E, 64] fp32
    const int*   nbr  = (const int*)d_in[1];     // [P, 2]  int32
    const float* Kmat = (const float*)d_in[2];   // [64, 64] fp32
    const float* bias = (const float*)d_in[3];   // [64] fp32
    float* out = (float*)d_out;                  // [E, 64] fp32

    k_zero_cnt<<<(E_CNT / 4 + 255) / 256, 256>>>();
    k_hist<<<P_CNT / 256, 256>>>((const int2*)nbr);
    k_scan_block<<<NSCAN, SCAN_BLK>>>();
    k_scan_add<<<(E_CNT + 255) / 256, 256>>>();
    k_reorder<<<P_CNT / 256, 256>>>((const int2*)nbr);
    k_fused<<<E_CNT / 8, 256>>>((const float2*)feat, Kmat, bias, out);
}